// round 3
// baseline (speedup 1.0000x reference)
#include <cuda_runtime.h>
#include <cstddef>

#define TPB 256
#define MAX_PART 512
#define MAX_B 16
#define MAX_M 64

// Per-block partial sums: [batch][block] -> deterministic reduction, no atomics.
__device__ float g_cls [MAX_B * MAX_PART];
__device__ float g_corr[MAX_B * MAX_PART];
__device__ float g_reg [MAX_B * MAX_PART];
__device__ float g_cnt [MAX_B * MAX_PART];

__device__ __forceinline__ float sl1f(float d) {
    return d < 1.f ? 0.5f * d * d : d - 0.5f;
}

// Fused kernel: per (batch, anchor) -> IoU state vs M boxes, masked focal sum,
// rare-path pos corrections + regression loss.
// Grid: (blocksPerBatch, B). Each thread owns anchors via grid-stride.
template<int M_FIX, int C_FIX>
__global__ void __launch_bounds__(TPB)
fused_kernel(const float* __restrict__ cls,
             const float* __restrict__ rgr,
             const float* __restrict__ anchors,
             const float* __restrict__ ann,
             int N, int C, int M)
{
    const int b   = blockIdx.y;
    const int tid = threadIdx.x;
    const int Mr  = M_FIX ? M_FIX : ((M < MAX_M) ? M : MAX_M);
    const int Cr  = C_FIX ? C_FIX : C;

    __shared__ float4 s_box[MAX_M];   // x1,y1,x2,y2
    __shared__ float2 s_ac [MAX_M];   // area_b, class_id

    for (int m = tid; m < Mr; m += TPB) {
        const float* a = ann + ((size_t)b * M + m) * 5;   // true stride M
        float x1 = a[0], y1 = a[1], x2 = a[2], y2 = a[3], cc = a[4];
        s_box[m] = make_float4(x1, y1, x2, y2);
        s_ac [m] = make_float2((x2 - x1) * (y2 - y1), cc);
    }
    __syncthreads();

    float t_focal = 0.f, t_corr = 0.f, t_reg = 0.f, t_cnt = 0.f;

    const int stride = gridDim.x * TPB;
    for (int n = blockIdx.x * TPB + tid; n < N; n += stride) {
        // anchor -> corners
        const float4 anc = __ldg((const float4*)(anchors + (size_t)n * 4));
        const float cx = anc.x, cy = anc.y, aw = anc.z, ah = anc.w;
        const float ax1 = cx - aw * 0.5f, ay1 = cy - ah * 0.5f;
        const float ax2 = cx + aw * 0.5f, ay2 = cy + ah * 0.5f;
        const float area_a = (ax2 - ax1) * (ay2 - ay1);

        // IoU thresholds without division:
        //   iou >= 0.5  <=>  3.0*inter - area_b >= area_a
        //   iou >  0.4  <=>  3.5*inter - area_b >  area_a
        float m05 = -3.4e38f, m04 = -3.4e38f;
        if (M_FIX) {
            #pragma unroll
            for (int m = 0; m < (M_FIX ? M_FIX : 1); m++) {
                float4 bb = s_box[m];
                float2 ac = s_ac[m];
                float ix = fminf(ax2, bb.z) - fmaxf(ax1, bb.x);
                float iy = fminf(ay2, bb.w) - fmaxf(ay1, bb.y);
                float inter = fmaxf(ix, 0.f) * fmaxf(iy, 0.f);
                m05 = fmaxf(m05, fmaf(3.0f, inter, -ac.x));
                m04 = fmaxf(m04, fmaf(3.5f, inter, -ac.x));
            }
        } else {
            for (int m = 0; m < Mr; m++) {
                float4 bb = s_box[m];
                float2 ac = s_ac[m];
                float ix = fminf(ax2, bb.z) - fmaxf(ax1, bb.x);
                float iy = fminf(ay2, bb.w) - fmaxf(ay1, bb.y);
                float inter = fmaxf(ix, 0.f) * fmaxf(iy, 0.f);
                m05 = fmaxf(m05, fmaf(3.0f, inter, -ac.x));
                m04 = fmaxf(m04, fmaf(3.5f, inter, -ac.x));
            }
        }
        const bool pos = (m05 >= area_a);
        const bool neg = !(m04 > area_a);
        const float maskf = (pos || neg) ? 1.f : 0.f;

        // Masked focal (labels==0 path for ALL classes):
        //   acc = sum_c u^2 * log2(1-u),  u = min(cls, 1-1e-4)
        // Lower clamp of the reference is negligible here (u^2*log1p(-u)->0).
        // Converted to the reference value by K = -0.75*ln2 in finalize.
        float acc = 0.f;
        const size_t rowoff = ((size_t)b * N + n) * Cr;
        if (C_FIX) {
            const float4* row = (const float4*)(cls + rowoff);
            #pragma unroll 5
            for (int j = 0; j < C_FIX / 4; j++) {
                float4 v = row[j];
                float u0 = fminf(v.x, 0.9999f);
                float u1 = fminf(v.y, 0.9999f);
                float u2 = fminf(v.z, 0.9999f);
                float u3 = fminf(v.w, 0.9999f);
                acc = fmaf(u0 * u0, __log2f(1.f - u0), acc);
                acc = fmaf(u1 * u1, __log2f(1.f - u1), acc);
                acc = fmaf(u2 * u2, __log2f(1.f - u2), acc);
                acc = fmaf(u3 * u3, __log2f(1.f - u3), acc);
            }
        } else {
            const float* row = cls + rowoff;
            for (int j = 0; j < Cr; j++) {
                float u = fminf(row[j], 0.9999f);
                acc = fmaf(u * u, __log2f(1.f - u), acc);
            }
        }
        t_focal += maskf * acc;

        // ---- rare path: positive anchor ----
        if (pos) {
            // exact argmax over boxes via cross-multiplied IoU comparison
            // (keeps first-max on ties, matching argmax semantics)
            float bi = -1.f, bu = 1.f;
            int bm = 0;
            for (int m = 0; m < Mr; m++) {
                float4 bb = s_box[m];
                float2 ac = s_ac[m];
                float ix = fminf(ax2, bb.z) - fmaxf(ax1, bb.x);
                float iy = fminf(ay2, bb.w) - fmaxf(ay1, bb.y);
                float inter = fmaxf(ix, 0.f) * fmaxf(iy, 0.f);
                float uni = area_a + ac.x - inter;
                if (inter * bu > bi * uni) { bi = inter; bu = uni; bm = m; }
            }
            float4 bb = s_box[bm];
            int cid = (int)s_ac[bm].y;

            // focal correction for the assigned class column:
            // remove the labels==0 term, add the labels==1 term (precise logs)
            float u = cls[rowoff + cid];
            u = fminf(fmaxf(u, 1e-4f), 0.9999f);
            float om = 1.f - u;
            float posterm = 0.25f * om * om * (-logf(u));
            float negterm = 0.75f * u * u * (-log1pf(-u));
            t_corr += posterm - negterm;
            t_cnt  += 1.f;

            // regression smooth-L1 (replicates reference exactly, incl.
            // the dx = x1 + x2/2 "center" formula quirk)
            float dwb = bb.z - bb.x, dhb = bb.w - bb.y;
            float dxb = bb.x + bb.z * 0.5f;
            float dyb = bb.y + bb.w * 0.5f;
            float dx = (dxb - cx) / aw;
            float dy = (dyb - cy) / ah;
            float dw = logf(dwb / aw);
            float dh = logf(dhb / ah);
            const float4 rg = __ldg((const float4*)(rgr + ((size_t)b * N + n) * 4));
            float d0 = fabsf(rg.x / 0.1f - dx / 0.1f);
            float d1 = fabsf(rg.y / 0.1f - dy / 0.1f);
            float d2 = fabsf(rg.z / 0.2f - dw / 0.2f);
            float d3 = fabsf(rg.w / 0.2f - dh / 0.2f);
            t_reg += sl1f(d0) + sl1f(d1) + sl1f(d2) + sl1f(d3);
        }
    }

    // deterministic block tree reduction of 4 accumulators
    __shared__ float4 red[TPB];
    red[tid] = make_float4(t_focal, t_corr, t_reg, t_cnt);
    __syncthreads();
    #pragma unroll
    for (int off = TPB / 2; off > 0; off >>= 1) {
        if (tid < off) {
            float4 x = red[tid], y = red[tid + off];
            red[tid] = make_float4(x.x + y.x, x.y + y.y, x.z + y.z, x.w + y.w);
        }
        __syncthreads();
    }
    if (tid == 0) {
        int p = b * MAX_PART + blockIdx.x;
        g_cls [p] = red[0].x;
        g_corr[p] = red[0].y;
        g_reg [p] = red[0].z;
        g_cnt [p] = red[0].w;
    }
}

__global__ void __launch_bounds__(TPB)
finalize_kernel(float* __restrict__ out, int B, int nPart, int out_size)
{
    __shared__ float4 red[TPB];
    __shared__ float cls_b[MAX_B], corr_b[MAX_B], reg_b[MAX_B], cnt_b[MAX_B];
    const int tid = threadIdx.x;

    for (int b = 0; b < B; b++) {
        float a0 = 0.f, a1 = 0.f, a2 = 0.f, a3 = 0.f;
        for (int i = tid; i < nPart; i += TPB) {
            int p = b * MAX_PART + i;
            a0 += g_cls[p]; a1 += g_corr[p]; a2 += g_reg[p]; a3 += g_cnt[p];
        }
        red[tid] = make_float4(a0, a1, a2, a3);
        __syncthreads();
        #pragma unroll
        for (int off = TPB / 2; off > 0; off >>= 1) {
            if (tid < off) {
                float4 x = red[tid], y = red[tid + off];
                red[tid] = make_float4(x.x + y.x, x.y + y.y, x.z + y.z, x.w + y.w);
            }
            __syncthreads();
        }
        if (tid == 0) {
            cls_b[b] = red[0].x; corr_b[b] = red[0].y;
            reg_b[b] = red[0].z; cnt_b[b]  = red[0].w;
        }
        __syncthreads();
    }

    if (tid == 0) {
        // main pass accumulated sum(u^2*log2(1-u)); convert:
        // cls_sum = -0.75*ln2 * S + corrections
        const float K = -0.75f * 0.69314718055994531f;
        float clsm = 0.f, es = 0.f, ec = 0.f;
        for (int b = 0; b < B; b++) {
            float cnt = cnt_b[b];
            float denom = fmaxf(cnt, 1.f);
            clsm += (K * cls_b[b] + corr_b[b]) / denom;
            if (cnt > 0.f) {
                float rm = reg_b[b] / (denom * 4.f);
                es += rm / denom + rm;
                ec += 2.f;
            } else {
                ec += 1.f;
            }
        }
        if (out_size >= 1) out[0] = clsm / (float)B;
        if (out_size >= 2) out[1] = es / ec;
    }
}

extern "C" void kernel_launch(void* const* d_in, const int* in_sizes, int n_in,
                              void* d_out, int out_size)
{
    // Identify inputs by element count (robust to metadata ordering):
    //   classifications = B*N*C (largest)
    //   regressions     = B*N*4
    //   anchors         = N*4
    //   annotations     = B*M*5 (smallest)
    int order[4] = {0, 1, 2, 3};
    for (int i = 0; i < 3; i++)
        for (int j = i + 1; j < 4; j++)
            if ((long long)in_sizes[order[j]] > (long long)in_sizes[order[i]]) {
                int t = order[i]; order[i] = order[j]; order[j] = t;
            }
    const int iCls = order[0], iReg = order[1], iAnc = order[2], iAnn = order[3];

    const float* cls     = (const float*)d_in[iCls];
    const float* rgr     = (const float*)d_in[iReg];
    const float* anchors = (const float*)d_in[iAnc];
    const float* ann     = (const float*)d_in[iAnn];

    const long long szCls = in_sizes[iCls];
    const long long szReg = in_sizes[iReg];
    const long long szAnc = in_sizes[iAnc];
    const long long szAnn = in_sizes[iAnn];

    const int N = (int)(szAnc / 4);
    const int B = (int)(szReg / (4LL * N));
    const int C = (int)(szCls / ((long long)B * N));
    const int M = (int)(szAnn / (5LL * B));

    int blocksPerBatch = (N + TPB - 1) / TPB;
    if (blocksPerBatch > MAX_PART) blocksPerBatch = MAX_PART;

    dim3 grid(blocksPerBatch, B);
    if (M == 32 && C == 80) {
        fused_kernel<32, 80><<<grid, TPB>>>(cls, rgr, anchors, ann, N, C, M);
    } else {
        fused_kernel<0, 0><<<grid, TPB>>>(cls, rgr, anchors, ann, N, C, M);
    }
    finalize_kernel<<<1, TPB>>>((float*)d_out, B, blocksPerBatch, out_size);
}

// round 6
// speedup vs baseline: 1.1488x; 1.1488x over previous
#include <cuda_runtime.h>
#include <cstddef>

#define TPB 256
#define WPB 8            // warps per block
#define MAX_PART 512
#define MAX_B 16
#define MAX_M 64

// Per-block partial sums: [batch][block]; deterministic fixed-order reduction.
__device__ float g_cls [MAX_B * MAX_PART];
__device__ float g_corr[MAX_B * MAX_PART];
__device__ float g_reg [MAX_B * MAX_PART];
__device__ float g_cnt [MAX_B * MAX_PART];

__device__ __forceinline__ float sl1f(float d) {
    return d < 1.f ? 0.5f * d * d : d - 0.5f;
}

// Block epilogue: deterministic tree reduction, write per-block partials.
__device__ void block_epilogue(float t_focal, float t_corr, float t_reg,
                               float t_cnt, int b)
{
    const int tid = threadIdx.x;
    __shared__ float4 red[TPB];
    red[tid] = make_float4(t_focal, t_corr, t_reg, t_cnt);
    __syncthreads();
    #pragma unroll
    for (int off = TPB / 2; off > 0; off >>= 1) {
        if (tid < off) {
            float4 x = red[tid], y = red[tid + off];
            red[tid] = make_float4(x.x + y.x, x.y + y.y, x.z + y.z, x.w + y.w);
        }
        __syncthreads();
    }
    if (tid == 0) {
        int p = b * MAX_PART + blockIdx.x;
        g_cls [p] = red[0].x;
        g_corr[p] = red[0].y;
        g_reg [p] = red[0].z;
        g_cnt [p] = red[0].w;
    }
}

// ---------------------------------------------------------------------------
// Specialized fused kernel: M=32, C=80. Warp-cooperative, fully coalesced
// streaming of each warp's 32-anchor x 80-class block.
// ---------------------------------------------------------------------------
__global__ void __launch_bounds__(TPB)
fused_kernel_spec(const float* __restrict__ cls,
                  const float* __restrict__ rgr,
                  const float* __restrict__ anchors,
                  const float* __restrict__ ann,
                  int N, int B)
{
    constexpr int M  = 32;
    constexpr int C4 = 20;      // 80 floats = 20 float4 per anchor
    const int b    = blockIdx.y;
    const int tid  = threadIdx.x;
    const int lane = tid & 31;
    const int wid  = tid >> 5;

    __shared__ float4 s_box[M];   // x1,y1,x2,y2
    __shared__ float2 s_ac [M];   // area_b, class_id

    if (tid < M) {
        const float* a = ann + ((size_t)b * M + tid) * 5;
        float x1 = a[0], y1 = a[1], x2 = a[2], y2 = a[3], cc = a[4];
        s_box[tid] = make_float4(x1, y1, x2, y2);
        s_ac [tid] = make_float2((x2 - x1) * (y2 - y1), cc);
    }
    __syncthreads();

    float t_focal = 0.f, t_corr = 0.f, t_reg = 0.f, t_cnt = 0.f;

    const int tilesPerBatch = (N + 31) / 32;
    for (int tile = blockIdx.x * WPB + wid; tile < tilesPerBatch;
         tile += gridDim.x * WPB)
    {
        const int tb = tile * 32;
        const int n  = tb + lane;
        const bool fullTile = (tb + 32 <= N);
        const bool valid = (n < N);

        float maskf = 0.f;
        bool  pos   = false;
        float cx = 0.f, cy = 0.f, aw = 1.f, ah = 1.f;
        float ax1 = 0.f, ay1 = 0.f, ax2 = 0.f, ay2 = 0.f, area_a = 0.f;

        if (valid) {
            const float4 anc = __ldg((const float4*)(anchors + (size_t)n * 4));
            cx = anc.x; cy = anc.y; aw = anc.z; ah = anc.w;
            ax1 = cx - aw * 0.5f; ay1 = cy - ah * 0.5f;
            ax2 = cx + aw * 0.5f; ay2 = cy + ah * 0.5f;
            area_a = (ax2 - ax1) * (ay2 - ay1);

            // Division-free thresholds:
            //   iou >= 0.5  <=>  3.0*inter - area_b >= area_a
            //   iou >  0.4  <=>  3.5*inter - area_b >  area_a
            float m05 = -3.4e38f, m04 = -3.4e38f;
            #pragma unroll
            for (int m = 0; m < M; m++) {
                float4 bb = s_box[m];
                float2 ac = s_ac[m];
                float ix = fminf(ax2, bb.z) - fmaxf(ax1, bb.x);
                float iy = fminf(ay2, bb.w) - fmaxf(ay1, bb.y);
                float inter = fmaxf(ix, 0.f) * fmaxf(iy, 0.f);
                m05 = fmaxf(m05, fmaf(3.0f, inter, -ac.x));
                m04 = fmaxf(m04, fmaf(3.5f, inter, -ac.x));
            }
            pos = (m05 >= area_a);
            const bool neg = !(m04 > area_a);
            maskf = (pos || neg) ? 1.f : 0.f;
        }

        // -------- coalesced focal stream over the warp's 32x80 block --------
        // acc += mask(anchor) * u^2 * log2(1-u) per element; converted to the
        // reference's sum by K = -0.75*ln2 in finalize.
        const float4* row4 = (const float4*)cls + ((size_t)b * N + tb) * C4;
        float acc = 0.f;

        if (fullTile) {
            // hot path: unpredicated, perfectly coalesced
            #pragma unroll 5
            for (int k = 0; k < C4; k++) {
                const int f = k * 32 + lane;
                const float4 v = __ldg(row4 + f);
                const int a = f / C4;                   // owning anchor lane
                const float mk = __shfl_sync(0xffffffffu, maskf, a);
                float u0 = fminf(v.x, 0.9999f);
                float u1 = fminf(v.y, 0.9999f);
                float u2 = fminf(v.z, 0.9999f);
                float u3 = fminf(v.w, 0.9999f);
                float p;
                p = (u0 * u0) * __log2f(1.f - u0);
                p = fmaf(u1 * u1, __log2f(1.f - u1), p);
                p = fmaf(u2 * u2, __log2f(1.f - u2), p);
                p = fmaf(u3 * u3, __log2f(1.f - u3), p);
                acc = fmaf(mk, p, acc);
            }
        } else {
            const int limit = (N - tb) * C4;   // valid float4 count
            for (int k = 0; k < C4; k++) {
                const int f = k * 32 + lane;
                float4 v = make_float4(0.f, 0.f, 0.f, 0.f);
                if (f < limit) v = __ldg(row4 + f);
                const int a = f / C4;
                const float mk = __shfl_sync(0xffffffffu, maskf, a);
                float u0 = fminf(v.x, 0.9999f);
                float u1 = fminf(v.y, 0.9999f);
                float u2 = fminf(v.z, 0.9999f);
                float u3 = fminf(v.w, 0.9999f);
                float p;
                p = (u0 * u0) * __log2f(1.f - u0);
                p = fmaf(u1 * u1, __log2f(1.f - u1), p);
                p = fmaf(u2 * u2, __log2f(1.f - u2), p);
                p = fmaf(u3 * u3, __log2f(1.f - u3), p);
                acc = fmaf(mk, p, acc);
            }
        }
        t_focal += acc;

        // -------------------- rare path: positive anchors -------------------
        if (pos) {
            // exact argmax via cross-multiplied IoU comparison (first-max ties)
            float bi = -1.f, bu = 1.f;
            int bm = 0;
            #pragma unroll
            for (int m = 0; m < M; m++) {
                float4 bb = s_box[m];
                float2 ac = s_ac[m];
                float ix = fminf(ax2, bb.z) - fmaxf(ax1, bb.x);
                float iy = fminf(ay2, bb.w) - fmaxf(ay1, bb.y);
                float inter = fmaxf(ix, 0.f) * fmaxf(iy, 0.f);
                float uni = area_a + ac.x - inter;
                if (inter * bu > bi * uni) { bi = inter; bu = uni; bm = m; }
            }
            float4 bb = s_box[bm];
            int cid = (int)s_ac[bm].y;

            // focal correction for the assigned class column:
            // remove the labels==0 term, add the labels==1 term (precise logs)
            float u = cls[((size_t)b * N + n) * 80 + cid];
            u = fminf(fmaxf(u, 1e-4f), 0.9999f);
            float om = 1.f - u;
            float posterm = 0.25f * om * om * (-logf(u));
            float negterm = 0.75f * u * u * (-log1pf(-u));
            t_corr += posterm - negterm;
            t_cnt  += 1.f;

            // regression smooth-L1 (replicates reference exactly,
            // including the dx = x1 + x2/2 center quirk)
            float dwb = bb.z - bb.x, dhb = bb.w - bb.y;
            float dxb = bb.x + bb.z * 0.5f;
            float dyb = bb.y + bb.w * 0.5f;
            float dx = (dxb - cx) / aw;
            float dy = (dyb - cy) / ah;
            float dw = logf(dwb / aw);
            float dh = logf(dhb / ah);
            const float4 rg = __ldg((const float4*)(rgr + ((size_t)b * N + n) * 4));
            float d0 = fabsf(rg.x / 0.1f - dx / 0.1f);
            float d1 = fabsf(rg.y / 0.1f - dy / 0.1f);
            float d2 = fabsf(rg.z / 0.2f - dw / 0.2f);
            float d3 = fabsf(rg.w / 0.2f - dh / 0.2f);
            t_reg += sl1f(d0) + sl1f(d1) + sl1f(d2) + sl1f(d3);
        }
    }

    block_epilogue(t_focal, t_corr, t_reg, t_cnt, b);
}

// ---------------------------------------------------------------------------
// Generic fallback (any M <= MAX_M, any C): per-thread anchor processing.
// ---------------------------------------------------------------------------
__global__ void __launch_bounds__(TPB)
fused_kernel_gen(const float* __restrict__ cls,
                 const float* __restrict__ rgr,
                 const float* __restrict__ anchors,
                 const float* __restrict__ ann,
                 int N, int B, int C, int M)
{
    const int b   = blockIdx.y;
    const int tid = threadIdx.x;
    const int Mr  = (M < MAX_M) ? M : MAX_M;

    __shared__ float4 s_box[MAX_M];
    __shared__ float2 s_ac [MAX_M];
    for (int m = tid; m < Mr; m += TPB) {
        const float* a = ann + ((size_t)b * M + m) * 5;
        float x1 = a[0], y1 = a[1], x2 = a[2], y2 = a[3], cc = a[4];
        s_box[m] = make_float4(x1, y1, x2, y2);
        s_ac [m] = make_float2((x2 - x1) * (y2 - y1), cc);
    }
    __syncthreads();

    float t_focal = 0.f, t_corr = 0.f, t_reg = 0.f, t_cnt = 0.f;
    const int stride = gridDim.x * TPB;
    for (int n = blockIdx.x * TPB + tid; n < N; n += stride) {
        const float4 anc = __ldg((const float4*)(anchors + (size_t)n * 4));
        const float cx = anc.x, cy = anc.y, aw = anc.z, ah = anc.w;
        const float ax1 = cx - aw * 0.5f, ay1 = cy - ah * 0.5f;
        const float ax2 = cx + aw * 0.5f, ay2 = cy + ah * 0.5f;
        const float area_a = (ax2 - ax1) * (ay2 - ay1);

        float m05 = -3.4e38f, m04 = -3.4e38f;
        for (int m = 0; m < Mr; m++) {
            float4 bb = s_box[m];
            float2 ac = s_ac[m];
            float ix = fminf(ax2, bb.z) - fmaxf(ax1, bb.x);
            float iy = fminf(ay2, bb.w) - fmaxf(ay1, bb.y);
            float inter = fmaxf(ix, 0.f) * fmaxf(iy, 0.f);
            m05 = fmaxf(m05, fmaf(3.0f, inter, -ac.x));
            m04 = fmaxf(m04, fmaf(3.5f, inter, -ac.x));
        }
        const bool pos = (m05 >= area_a);
        const bool neg = !(m04 > area_a);
        const float maskf = (pos || neg) ? 1.f : 0.f;

        float acc = 0.f;
        const size_t rowoff = ((size_t)b * N + n) * C;
        const float* row = cls + rowoff;
        for (int j = 0; j < C; j++) {
            float u = fminf(row[j], 0.9999f);
            acc = fmaf(u * u, __log2f(1.f - u), acc);
        }
        t_focal += maskf * acc;

        if (pos) {
            float bi = -1.f, bu = 1.f;
            int bm = 0;
            for (int m = 0; m < Mr; m++) {
                float4 bb = s_box[m];
                float2 ac = s_ac[m];
                float ix = fminf(ax2, bb.z) - fmaxf(ax1, bb.x);
                float iy = fminf(ay2, bb.w) - fmaxf(ay1, bb.y);
                float inter = fmaxf(ix, 0.f) * fmaxf(iy, 0.f);
                float uni = area_a + ac.x - inter;
                if (inter * bu > bi * uni) { bi = inter; bu = uni; bm = m; }
            }
            float4 bb = s_box[bm];
            int cid = (int)s_ac[bm].y;

            float u = row[cid];
            u = fminf(fmaxf(u, 1e-4f), 0.9999f);
            float om = 1.f - u;
            float posterm = 0.25f * om * om * (-logf(u));
            float negterm = 0.75f * u * u * (-log1pf(-u));
            t_corr += posterm - negterm;
            t_cnt  += 1.f;

            float dwb = bb.z - bb.x, dhb = bb.w - bb.y;
            float dxb = bb.x + bb.z * 0.5f;
            float dyb = bb.y + bb.w * 0.5f;
            float dx = (dxb - cx) / aw;
            float dy = (dyb - cy) / ah;
            float dw = logf(dwb / aw);
            float dh = logf(dhb / ah);
            const float4 rg = __ldg((const float4*)(rgr + ((size_t)b * N + n) * 4));
            float d0 = fabsf(rg.x / 0.1f - dx / 0.1f);
            float d1 = fabsf(rg.y / 0.1f - dy / 0.1f);
            float d2 = fabsf(rg.z / 0.2f - dw / 0.2f);
            float d3 = fabsf(rg.w / 0.2f - dh / 0.2f);
            t_reg += sl1f(d0) + sl1f(d1) + sl1f(d2) + sl1f(d3);
        }
    }

    block_epilogue(t_focal, t_corr, t_reg, t_cnt, b);
}

// ---------------------------------------------------------------------------
// Finalize: one warp per batch (parallel), single barrier, thread 0 combines.
// ---------------------------------------------------------------------------
__global__ void __launch_bounds__(TPB)
finalize_kernel(float* __restrict__ out, int B, int nPart, int out_size)
{
    __shared__ float s_cls[MAX_B], s_corr[MAX_B], s_reg[MAX_B], s_cnt[MAX_B];
    const int tid  = threadIdx.x;
    const int w    = tid >> 5;
    const int lane = tid & 31;

    for (int b = w; b < B; b += WPB) {
        float a0 = 0.f, a1 = 0.f, a2 = 0.f, a3 = 0.f;
        for (int i = lane; i < nPart; i += 32) {
            int p = b * MAX_PART + i;
            a0 += g_cls[p]; a1 += g_corr[p]; a2 += g_reg[p]; a3 += g_cnt[p];
        }
        #pragma unroll
        for (int off = 16; off; off >>= 1) {
            a0 += __shfl_down_sync(0xffffffffu, a0, off);
            a1 += __shfl_down_sync(0xffffffffu, a1, off);
            a2 += __shfl_down_sync(0xffffffffu, a2, off);
            a3 += __shfl_down_sync(0xffffffffu, a3, off);
        }
        if (lane == 0) { s_cls[b] = a0; s_corr[b] = a1; s_reg[b] = a2; s_cnt[b] = a3; }
    }
    __syncthreads();

    if (tid == 0) {
        // main pass accumulated sum(u^2*log2(1-u)); convert via K = -0.75*ln2
        const float K = -0.75f * 0.69314718055994531f;
        float clsm = 0.f, es = 0.f, ec = 0.f;
        for (int b = 0; b < B; b++) {
            float cnt = s_cnt[b];
            float denom = fmaxf(cnt, 1.f);
            clsm += (K * s_cls[b] + s_corr[b]) / denom;
            if (cnt > 0.f) {
                float rm = s_reg[b] / (denom * 4.f);
                es += rm / denom + rm;
                ec += 2.f;
            } else {
                ec += 1.f;
            }
        }
        if (out_size >= 1) out[0] = clsm / (float)B;
        if (out_size >= 2) out[1] = es / ec;
    }
}

extern "C" void kernel_launch(void* const* d_in, const int* in_sizes, int n_in,
                              void* d_out, int out_size)
{
    // Identify inputs by element count (robust to metadata ordering):
    //   classifications = B*N*C (largest), regressions = B*N*4,
    //   anchors = N*4, annotations = B*M*5 (smallest)
    int order[4] = {0, 1, 2, 3};
    for (int i = 0; i < 3; i++)
        for (int j = i + 1; j < 4; j++)
            if ((long long)in_sizes[order[j]] > (long long)in_sizes[order[i]]) {
                int t = order[i]; order[i] = order[j]; order[j] = t;
            }
    const int iCls = order[0], iReg = order[1], iAnc = order[2], iAnn = order[3];

    const float* cls     = (const float*)d_in[iCls];
    const float* rgr     = (const float*)d_in[iReg];
    const float* anchors = (const float*)d_in[iAnc];
    const float* ann     = (const float*)d_in[iAnn];

    const long long szCls = in_sizes[iCls];
    const long long szReg = in_sizes[iReg];
    const long long szAnc = in_sizes[iAnc];
    const long long szAnn = in_sizes[iAnn];

    const int N = (int)(szAnc / 4);
    const int B = (int)(szReg / (4LL * N));
    const int C = (int)(szCls / ((long long)B * N));
    const int M = (int)(szAnn / (5LL * B));

    int blocksPerBatch;
    if (M == 32 && C == 80 && B <= MAX_B) {
        const int tilesPerBatch = (N + 31) / 32;
        blocksPerBatch = (tilesPerBatch + WPB - 1) / WPB;
        if (blocksPerBatch > MAX_PART) blocksPerBatch = MAX_PART;
        dim3 grid(blocksPerBatch, B);
        fused_kernel_spec<<<grid, TPB>>>(cls, rgr, anchors, ann, N, B);
    } else {
        blocksPerBatch = (N + TPB - 1) / TPB;
        if (blocksPerBatch > MAX_PART) blocksPerBatch = MAX_PART;
        dim3 grid(blocksPerBatch, B);
        fused_kernel_gen<<<grid, TPB>>>(cls, rgr, anchors, ann, N, B, C, M);
    }
    finalize_kernel<<<1, TPB>>>((float*)d_out, B, blocksPerBatch, out_size);
}